// round 11
// baseline (speedup 1.0000x reference)
#include <cuda_runtime.h>
#include <cuda_bf16.h>

// Problem constants
#define NI 64
#define NO 64
#define NN 1024
#define NB 16384
#define NWARM 25
#define JCOLS 960   // j in [64,1024)
#define WK 896      // regulator rows k in [128,1024)

// ---------------- device scratch (no allocations allowed) ----------------
__device__ float4 g_jc[JCOLS];      // per-col: {dscale*E1, dscale*E2, c, bits(qe|qi<<16)}
__device__ float g_cs0[JCOLS];      // (1/N) * sum_{k<64} S[k][j]  (for warmup)
__device__ float g_E1[JCOLS], g_E2[JCOLS];   // e^{-b id_j}, e^{+b id_j}
// warmup factorization tables (k>=128), sorted order
__device__ float g_sWe[WK], g_sVe[WK];
__device__ float g_sWi[WK], g_sVi[WK];
__device__ int   g_Ge[WK], g_Gi[WK];
__device__ int   g_Pe[JCOLS], g_Pi[JCOLS];
// batch factorization tables (k<64), sorted order
__device__ float g_we64[64], g_ve64[64], g_wi64[64], g_vi64[64];
__device__ int   g_bge[64], g_bgi[64];

// ---------------- kernel A: per-column constants + sort/rank tables ------
// block-per-column: 960 blocks x 128 threads
__global__ void __launch_bounds__(128) kprep(const float* __restrict__ ident,
                      const float* __restrict__ enh,
                      const float* __restrict__ inh,
                      const float* __restrict__ beta,
                      const float* __restrict__ delta) {
    const int g = blockIdx.x;                    // 0..959 (column jrel & element id)
    const int tid = threadIdx.x, lane = tid & 31, wid = tid >> 5;
    const float b = beta[0];
    const float dscale = delta[0] * (1.0f / (float)NN);
    const float y = __ldg(&ident[NI + g]);

    const bool small = (g < 64);
    float eb = 0.f, ib = 0.f;
    if (small) { eb = __ldg(&enh[g]); ib = __ldg(&inh[g]); }

    // small part k<64: threads 0..63, one k each
    float cs = 0.f;
    int p1 = 0;   // qe | qi<<8 | r64e<<16 | r64i<<24
    if (tid < 64) {
        float ev = __ldg(&enh[tid]), iv = __ldg(&inh[tid]);
        cs = __expf(-b * fabsf(ev - y)) - __expf(-b * fabsf(iv - y));
        p1  = (ev < y) ? 1 : 0;
        p1 += (iv < y) ? (1 << 8) : 0;
        if (small) {
            p1 += ((ev < eb) || (ev == eb && tid < g)) ? (1 << 16) : 0;
            p1 += ((iv < ib) || (iv == ib && tid < g)) ? (1 << 24) : 0;
        }
    }

    // big part k>=128: 7 elems per thread
    const bool dorank = (g < WK);
    float ue = 0.f, ui = 0.f;
    if (dorank) { ue = __ldg(&enh[128 + g]); ui = __ldg(&inh[128 + g]); }
    int p2 = 0;   // cE | cI<<16
    int p3 = 0;   // rE | rI<<16
    #pragma unroll 7
    for (int m = tid; m < WK; m += 128) {
        float ae = __ldg(&enh[128 + m]), ai = __ldg(&inh[128 + m]);
        p2 += ((ae < y) ? 1 : 0) + ((ai < y) ? (1 << 16) : 0);
        if (dorank) {
            p3 += (((ae < ue) || (ae == ue && m < g)) ? 1 : 0)
                + (((ai < ui) || (ai == ui && m < g)) ? (1 << 16) : 0);
        }
    }

    #pragma unroll
    for (int o = 16; o > 0; o >>= 1) {
        cs += __shfl_xor_sync(0xffffffffu, cs, o);
        p1 += __shfl_xor_sync(0xffffffffu, p1, o);
        p2 += __shfl_xor_sync(0xffffffffu, p2, o);
        p3 += __shfl_xor_sync(0xffffffffu, p3, o);
    }
    __shared__ float scs[4];
    __shared__ int s1[4], s2[4], s3[4];
    if (lane == 0) { scs[wid] = cs; s1[wid] = p1; s2[wid] = p2; s3[wid] = p3; }
    __syncthreads();
    if (tid == 0) {
        float CS = (scs[0] + scs[1]) + (scs[2] + scs[3]);
        int P1 = s1[0] + s1[1] + s1[2] + s1[3];
        int P2 = s2[0] + s2[1] + s2[2] + s2[3];
        int P3 = s3[0] + s3[1] + s3[2] + s3[3];
        int qe = P1 & 0xff, qi = (P1 >> 8) & 0xff;
        int r64e = (P1 >> 16) & 0xff, r64i = (P1 >> 24) & 0xff;
        int cE = P2 & 0xffff, cI = P2 >> 16;
        int rE = P3 & 0xffff, rI = P3 >> 16;
        g_Pe[g] = cE;
        g_Pi[g] = cI;
        g_cs0[g] = CS * (1.0f / (float)NN);
        float e1 = __expf(-b * y), e2 = __expf(b * y);
        g_E1[g] = e1;
        g_E2[g] = e2;
        float4 jc;
        jc.x = dscale * e1;
        jc.y = dscale * e2;
        jc.z = 0.0f;                         // filled by kwarm
        jc.w = __int_as_float(qe | (qi << 16));
        g_jc[g] = jc;
        if (dorank) {
            g_sWe[rE] = __expf( b * ue);
            g_sVe[rE] = __expf(-b * ue);
            g_Ge[rE]  = 64 + g;
            g_sWi[rI] = __expf( b * ui);
            g_sVi[rI] = __expf(-b * ui);
            g_Gi[rI]  = 64 + g;
        }
        if (small) {
            g_bge[r64e] = g;
            g_we64[r64e] = __expf( b * eb);
            g_ve64[r64e] = __expf(-b * eb);
            g_bgi[r64i] = g;
            g_wi64[r64i] = __expf( b * ib);
            g_vi64[r64i] = __expf(-b * ib);
        }
    }
}

// ---------------- kernel B: warmup, 128 threads, 4 specialized warps -----
// warps 0,1: enhancer channels (elements [0,448),[448,896)); warps 2,3: inhibitor.
// Each lane owns 14 consecutive sorted elements; tables in registers.
// NOTE: launched TWICE this round — first launch is a timing probe whose
// outputs are dead (kprep rewrites g_jc fully; real kwarm rewrites .z).
__global__ void __launch_bounds__(128) kwarm(const float* __restrict__ delta) {
    __shared__ __align__(16) float4 p4[WK + 1];   // exclusive prefixes {Ae,Be,Ai,Bi}
    __shared__ float cbuf[2][JCOLS];
    __shared__ float2 wTot[4];
    __shared__ float warpS[4];

    const int tid = threadIdx.x, lane = tid & 31, wid = tid >> 5;
    const float dscale = delta[0] * (1.0f / (float)NN);
    const bool isE = (wid < 2);
    const int base = (wid & 1) * 448 + lane * 14;

    // iteration-invariant tables -> registers
    float Wt[14], Vt[14];
    int   idx[14];
    {
        const float* gw = isE ? g_sWe : g_sWi;
        const float* gv = isE ? g_sVe : g_sVi;
        const int*   gi = isE ? g_Ge  : g_Gi;
        #pragma unroll
        for (int u = 0; u < 14; u++) {
            Wt[u] = __ldg(&gw[base + u]);
            Vt[u] = __ldg(&gv[base + u]);
            idx[u] = __ldg(&gi[base + u]);
        }
    }
    // per-column constants: 8 cols per thread (j = tid + 128*q)
    int   ppk[8];
    float e1r[8], e2r[8], cs0r[8];
    #pragma unroll
    for (int q = 0; q < 8; q++) {
        int j = tid + 128 * q;
        if (j < JCOLS) {
            ppk[q]  = g_Pe[j] | (g_Pi[j] << 16);
            e1r[q]  = g_E1[j];
            e2r[q]  = g_E2[j];
            cs0r[q] = g_cs0[j];
        } else {
            ppk[q] = 0; e1r[q] = 0.f; e2r[q] = 0.f; cs0r[q] = 0.f;
        }
    }
    for (int i = tid; i < JCOLS; i += 128) cbuf[0][i] = 1.0f / (float)NN;
    __syncthreads();

    int cur = 0;
    float s = 1.0f;
    for (int t = 0; t <= NWARM; t++) {
        float inv = (s > 0.0f) ? (1.0f / s) : 1.0f;

        // local exclusive prefix over 14 elements (2 channels)
        float la[14], lb[14];
        float pa = 0.f, pb = 0.f;
        #pragma unroll
        for (int u = 0; u < 14; u++) {
            la[u] = pa; lb[u] = pb;
            float c = cbuf[cur][idx[u]];
            pa = fmaf(c, Wt[u], pa);
            pb = fmaf(c, Vt[u], pb);
        }
        // warp inclusive scan of thread totals
        float ix = pa, iy = pb;
        #pragma unroll
        for (int o = 1; o < 32; o <<= 1) {
            float x = __shfl_up_sync(0xffffffffu, ix, o);
            float y = __shfl_up_sync(0xffffffffu, iy, o);
            if (lane >= o) { ix += x; iy += y; }
        }
        if (lane == 31) wTot[wid] = make_float2(ix, iy);
        __syncthreads();
        float ox = ix - pa, oy = iy - pb;            // exclusive of own total
        if (wid & 1) { ox += wTot[wid - 1].x; oy += wTot[wid - 1].y; }
        // store exclusive prefixes for this segment
        if (isE) {
            #pragma unroll
            for (int u = 0; u < 14; u++)
                *(float2*)&p4[base + u].x = make_float2(ox + la[u], oy + lb[u]);
            if (wid == 1 && lane == 31)
                *(float2*)&p4[WK].x = make_float2(ox + pa, oy + pb);
        } else {
            #pragma unroll
            for (int u = 0; u < 14; u++)
                *(float2*)&p4[base + u].z = make_float2(ox + la[u], oy + lb[u]);
            if (wid == 3 && lane == 31)
                *(float2*)&p4[WK].z = make_float2(ox + pa, oy + pb);
        }
        __syncthreads();

        float4 grand = p4[WK];
        float gterm = grand.y - grand.w;
        float mys = 0.0f;
        #pragma unroll
        for (int q = 0; q < 8; q++) {
            int j = tid + 128 * q;
            if (j < JCOLS) {
                int pe = ppk[q] & 0xffff, pi = ppk[q] >> 16;
                float4 fe = p4[pe];
                float4 fi = p4[pi];
                float acc = e1r[q] * (fe.x - fi.z)
                          + e2r[q] * ((fi.w - fe.y) + gterm);
                float bse = cbuf[cur][j] * inv;
                if (t < NWARM) {
                    float nv = fmaxf(bse + dscale * (cs0r[q] + inv * acc), 0.0f);
                    cbuf[cur ^ 1][j] = nv;
                    mys += nv;
                } else {
                    g_jc[j].z = bse + dscale * (inv * acc);   // bias for batch step
                }
            }
        }
        if (t == NWARM) break;

        #pragma unroll
        for (int o = 16; o > 0; o >>= 1) mys += __shfl_xor_sync(0xffffffffu, mys, o);
        if (lane == 0) warpS[wid] = mys;
        __syncthreads();
        s = (warpS[0] + warpS[1]) + (warpS[2] + warpS[3]);
        cur ^= 1;
    }
}

// ---------------- kernel C: batch step via factorized kernel evaluation --
struct MainSmem {
    float  Xs[64 * 32];       // [k][row]
    float2 Te[65 * 32];       // [pos][row]  (PAe, PBe)
    float2 Ti[65 * 32];       // [pos][row]  (PAi, PBi)
    float  Yout[64 * 32];     // [col][row]
    float  TBe[32], TBi[32];
    float  warpS[4][32];
    float  sInv[32];
};

__global__ void __launch_bounds__(128) kmain(const float* __restrict__ X,
                                             float* __restrict__ out) {
    extern __shared__ float _smraw[];
    MainSmem* S = (MainSmem*)_smraw;
    const int tid = threadIdx.x, lane = tid & 31, w = tid >> 5;
    const int rowbase = blockIdx.x * 32;

    {
        int r = tid >> 2, kq = (tid & 3) * 16;
        const float* xp = &X[(rowbase + r) * NI + kq];
        #pragma unroll
        for (int u = 0; u < 16; u += 4) {
            float4 vv = *(const float4*)&xp[u];
            S->Xs[(kq + u + 0) * 32 + r] = vv.x;
            S->Xs[(kq + u + 1) * 32 + r] = vv.y;
            S->Xs[(kq + u + 2) * 32 + r] = vv.z;
            S->Xs[(kq + u + 3) * 32 + r] = vv.w;
        }
    }
    __syncthreads();

    if (w < 2) {
        const int*   gp = (w == 0) ? g_bge : g_bgi;
        const float* gw = (w == 0) ? g_we64 : g_wi64;
        const float* gv = (w == 0) ? g_ve64 : g_vi64;
        float2* T = (w == 0) ? S->Te : S->Ti;
        float pa = 0.f, pb = 0.f;
        #pragma unroll 8
        for (int r = 0; r < 64; r++) {
            T[r * 32 + lane] = make_float2(pa, pb);
            float xv = S->Xs[__ldg(&gp[r]) * 32 + lane];
            pa = fmaf(xv, __ldg(&gw[r]), pa);
            pb = fmaf(xv, __ldg(&gv[r]), pb);
        }
        T[64 * 32 + lane] = make_float2(pa, pb);
        if (w == 0) S->TBe[lane] = pb; else S->TBi[lane] = pb;
    }
    __syncthreads();

    const float TBd = S->TBe[lane] - S->TBi[lane];
    float s = 0.f;
    #pragma unroll 4
    for (int j = w; j < JCOLS; j += 4) {
        float4 co = __ldg(&g_jc[j]);
        int qp = __float_as_int(co.w);
        float2 te = S->Te[(qp & 0xffff) * 32 + lane];
        float2 ti = S->Ti[(qp >> 16) * 32 + lane];
        float A  = te.x - ti.x;
        float Bv = TBd - (te.y - ti.y);
        float z  = fmaf(co.y, Bv, fmaf(co.x, A, co.z));
        float yv = fmaxf(z, 0.f);
        s += yv;
        if (j < 64) S->Yout[j * 32 + lane] = yv;
    }
    S->warpS[w][lane] = s;
    __syncthreads();
    if (w == 0) {
        float stot = S->warpS[0][lane] + S->warpS[1][lane]
                   + S->warpS[2][lane] + S->warpS[3][lane];
        S->sInv[lane] = (stot > 0.f) ? (1.0f / stot) : 1.0f;
    }
    __syncthreads();

    {
        int r = tid >> 2, c0 = (tid & 3) * 16;
        float inv = S->sInv[r];
        float* op = &out[(rowbase + r) * NO + c0];
        #pragma unroll
        for (int u = 0; u < 16; u += 4) {
            float4 vv = make_float4(S->Yout[(c0 + u + 0) * 32 + r] * inv,
                                    S->Yout[(c0 + u + 1) * 32 + r] * inv,
                                    S->Yout[(c0 + u + 2) * 32 + r] * inv,
                                    S->Yout[(c0 + u + 3) * 32 + r] * inv);
            *(float4*)&op[u] = vv;
        }
    }
}

// ---------------- launch ---------------------------------------------------
// DIAGNOSTIC THIS ROUND: kwarm is launched twice. The first launch (probe)
// runs before kprep; its table reads are stale-but-deterministic and every
// global it writes (g_jc[:].z) is fully overwritten by kprep (whole float4)
// and the second, real kwarm. Total-time delta vs the 78.3us baseline
// measures kwarm's true duration; ncu's captured first graph node becomes
// kwarm instead of kprep.
extern "C" void kernel_launch(void* const* d_in, const int* in_sizes, int n_in,
                              void* d_out, int out_size) {
    const float* X     = (const float*)d_in[0];  // (16384, 64)
    const float* ident = (const float*)d_in[1];  // (1024,)
    const float* enh   = (const float*)d_in[2];  // (1024,)
    const float* inh   = (const float*)d_in[3];  // (1024,)
    const float* beta  = (const float*)d_in[4];  // (1,)
    const float* delta = (const float*)d_in[5];  // (1,)
    (void)in_sizes; (void)n_in; (void)out_size;

    cudaFuncSetAttribute(kmain, cudaFuncAttributeMaxDynamicSharedMemorySize,
                         (int)sizeof(MainSmem));

    kwarm<<<1, 128>>>(delta);                    // timing probe (outputs dead)
    kprep<<<JCOLS, 128>>>(ident, enh, inh, beta, delta);
    kwarm<<<1, 128>>>(delta);                    // real warmup
    kmain<<<NB / 32, 128, sizeof(MainSmem)>>>(X, (float*)d_out);
}

// round 14
// speedup vs baseline: 1.4076x; 1.4076x over previous
#include <cuda_runtime.h>
#include <cuda_bf16.h>

// Problem constants
#define NI 64
#define NO 64
#define NN 1024
#define NB 16384
#define NWARM 25
#define JCOLS 960   // j in [64,1024)
#define WK 896      // regulator rows k in [128,1024)

// ---------------- device scratch (no allocations allowed) ----------------
__device__ float4 g_jc[JCOLS];      // per-col: {dscale*E1, dscale*E2, c, bits(qe|qi<<16)}
__device__ float g_cs0[JCOLS];      // dscale * (1/N) * sum_{k<64} S[k][j]
// warmup factorization tables (k>=128), sorted order
__device__ float g_sWe[WK], g_sVe[WK];
__device__ float g_sWi[WK], g_sVi[WK];
__device__ int   g_Ge[WK], g_Gi[WK];
__device__ int   g_Pe[JCOLS], g_Pi[JCOLS];   // BIG-part split positions (0..896)
// batch factorization tables (k<64), sorted order
__device__ float g_we64[64], g_ve64[64], g_wi64[64], g_vi64[64];
__device__ int   g_bge[64], g_bgi[64];

// ---------------- kernel A: per-column constants + sort/rank tables ------
// block-per-column: 960 blocks x 128 threads
__global__ void __launch_bounds__(128) kprep(const float* __restrict__ ident,
                      const float* __restrict__ enh,
                      const float* __restrict__ inh,
                      const float* __restrict__ beta,
                      const float* __restrict__ delta) {
    const int g = blockIdx.x;                    // 0..959 (column jrel & element id)
    const int tid = threadIdx.x, lane = tid & 31, wid = tid >> 5;
    const float b = beta[0];
    const float dscale = delta[0] * (1.0f / (float)NN);
    const float y = __ldg(&ident[NI + g]);

    const bool small = (g < 64);
    float eb = 0.f, ib = 0.f;
    if (small) { eb = __ldg(&enh[g]); ib = __ldg(&inh[g]); }

    // small part k<64: threads 0..63, one k each
    float cs = 0.f;
    int p1 = 0;   // qe | qi<<8 | r64e<<16 | r64i<<24
    if (tid < 64) {
        float ev = __ldg(&enh[tid]), iv = __ldg(&inh[tid]);
        cs = __expf(-b * fabsf(ev - y)) - __expf(-b * fabsf(iv - y));
        p1  = (ev < y) ? 1 : 0;
        p1 += (iv < y) ? (1 << 8) : 0;
        if (small) {
            p1 += ((ev < eb) || (ev == eb && tid < g)) ? (1 << 16) : 0;
            p1 += ((iv < ib) || (iv == ib && tid < g)) ? (1 << 24) : 0;
        }
    }

    // big part k>=128: 7 elems per thread
    const bool dorank = (g < WK);
    float ue = 0.f, ui = 0.f;
    if (dorank) { ue = __ldg(&enh[128 + g]); ui = __ldg(&inh[128 + g]); }
    int p2 = 0;   // cE | cI<<16
    int p3 = 0;   // rE | rI<<16
    #pragma unroll 7
    for (int m = tid; m < WK; m += 128) {
        float ae = __ldg(&enh[128 + m]), ai = __ldg(&inh[128 + m]);
        p2 += ((ae < y) ? 1 : 0) + ((ai < y) ? (1 << 16) : 0);
        if (dorank) {
            p3 += (((ae < ue) || (ae == ue && m < g)) ? 1 : 0)
                + (((ai < ui) || (ai == ui && m < g)) ? (1 << 16) : 0);
        }
    }

    #pragma unroll
    for (int o = 16; o > 0; o >>= 1) {
        cs += __shfl_xor_sync(0xffffffffu, cs, o);
        p1 += __shfl_xor_sync(0xffffffffu, p1, o);
        p2 += __shfl_xor_sync(0xffffffffu, p2, o);
        p3 += __shfl_xor_sync(0xffffffffu, p3, o);
    }
    __shared__ float scs[4];
    __shared__ int s1[4], s2[4], s3[4];
    if (lane == 0) { scs[wid] = cs; s1[wid] = p1; s2[wid] = p2; s3[wid] = p3; }
    __syncthreads();
    if (tid == 0) {
        float CS = (scs[0] + scs[1]) + (scs[2] + scs[3]);
        int P1 = s1[0] + s1[1] + s1[2] + s1[3];
        int P2 = s2[0] + s2[1] + s2[2] + s2[3];
        int P3 = s3[0] + s3[1] + s3[2] + s3[3];
        int qe = P1 & 0xff, qi = (P1 >> 8) & 0xff;
        int r64e = (P1 >> 16) & 0xff, r64i = (P1 >> 24) & 0xff;
        int cE = P2 & 0xffff, cI = P2 >> 16;
        int rE = P3 & 0xffff, rI = P3 >> 16;
        g_Pe[g] = cE;
        g_Pi[g] = cI;
        g_cs0[g] = CS * (1.0f / (float)NN) * dscale;
        float e1 = __expf(-b * y), e2 = __expf(b * y);
        float4 jc;
        jc.x = dscale * e1;
        jc.y = dscale * e2;
        jc.z = 0.0f;                         // filled by kwarm
        jc.w = __int_as_float(qe | (qi << 16));   // SMALL-part positions (kmain only)
        g_jc[g] = jc;
        if (dorank) {
            g_sWe[rE] = __expf( b * ue);
            g_sVe[rE] = __expf(-b * ue);
            g_Ge[rE]  = 64 + g;
            g_sWi[rI] = __expf( b * ui);
            g_sVi[rI] = __expf(-b * ui);
            g_Gi[rI]  = 64 + g;
        }
        if (small) {
            g_bge[r64e] = g;
            g_we64[r64e] = __expf( b * eb);
            g_ve64[r64e] = __expf(-b * eb);
            g_bgi[r64i] = g;
            g_wi64[r64i] = __expf( b * ib);
            g_vi64[r64i] = __expf(-b * ib);
        }
    }
}

// ---------------- kernel B: warmup, 2 warps, per-warp channel scan -------
// Warp 0 owns the whole enhancer channel (28 sorted elems/lane), warp 1 the
// inhibitor channel. Scans stay inside one warp: no cross-warp combine.
__global__ void __launch_bounds__(64) kwarm(const float* __restrict__ delta) {
    __shared__ __align__(16) float4 p4[WK + 1];   // exclusive prefixes {Ae,Be,Ai,Bi}
    __shared__ float cbuf[2][JCOLS];
    __shared__ float warpS[2];

    const int tid = threadIdx.x, lane = tid & 31, wid = tid >> 5;
    const bool isE = (wid == 0);
    const int base = lane * 28;

    // iteration-invariant tables -> registers (28 per lane)
    float Wt[28], Vt[28];
    int   idx[28];
    {
        const float* gw = isE ? g_sWe : g_sWi;
        const float* gv = isE ? g_sVe : g_sVi;
        const int*   gi = isE ? g_Ge  : g_Gi;
        #pragma unroll
        for (int u = 0; u < 28; u++) {
            Wt[u] = __ldg(&gw[base + u]);
            Vt[u] = __ldg(&gv[base + u]);
            idx[u] = __ldg(&gi[base + u]);
        }
    }
    for (int i = tid; i < JCOLS; i += 64) cbuf[0][i] = 1.0f / (float)NN;
    __syncthreads();

    int cur = 0;
    float s = 1.0f;
    for (int t = 0; t <= NWARM; t++) {
        float inv = (s > 0.0f) ? (1.0f / s) : 1.0f;

        // local exclusive prefix over 28 elements (2 channels per warp)
        float la[28], lb[28];
        float pa = 0.f, pb = 0.f;
        #pragma unroll
        for (int u = 0; u < 28; u++) {
            la[u] = pa; lb[u] = pb;
            float c = cbuf[cur][idx[u]];
            pa = fmaf(c, Wt[u], pa);
            pb = fmaf(c, Vt[u], pb);
        }
        // warp inclusive scan of thread totals (single warp: no combine)
        float ix = pa, iy = pb;
        #pragma unroll
        for (int o = 1; o < 32; o <<= 1) {
            float x = __shfl_up_sync(0xffffffffu, ix, o);
            float y = __shfl_up_sync(0xffffffffu, iy, o);
            if (lane >= o) { ix += x; iy += y; }
        }
        float ox = ix - pa, oy = iy - pb;            // exclusive of own total
        if (isE) {
            #pragma unroll
            for (int u = 0; u < 28; u++)
                *(float2*)&p4[base + u].x = make_float2(ox + la[u], oy + lb[u]);
            if (lane == 31)
                *(float2*)&p4[WK].x = make_float2(ix, iy);
        } else {
            #pragma unroll
            for (int u = 0; u < 28; u++)
                *(float2*)&p4[base + u].z = make_float2(ox + la[u], oy + lb[u]);
            if (lane == 31)
                *(float2*)&p4[WK].z = make_float2(ix, iy);
        }
        __syncthreads();

        float4 grand = p4[WK];
        float gterm = grand.y - grand.w;
        float mys = 0.0f;
        #pragma unroll
        for (int q = 0; q < 15; q++) {
            int j = tid + 64 * q;                    // covers 0..959
            float4 co = __ldg(&g_jc[j]);             // x=ds*E1, y=ds*E2
            // FIX (R13): kwarm must use the BIG-part split positions g_Pe/g_Pi
            // (0..896, indexing p4), NOT the small-part qpack in co.w.
            int pe = __ldg(&g_Pe[j]);
            int pi = __ldg(&g_Pi[j]);
            float4 fe = p4[pe];
            float4 fi = p4[pi];
            float acc2 = co.x * (fe.x - fi.z)
                       + co.y * ((fi.w - fe.y) + gterm);
            float bse = cbuf[cur][j] * inv;
            if (t < NWARM) {
                float nv = fmaxf(bse + __ldg(&g_cs0[j]) + inv * acc2, 0.0f);
                cbuf[cur ^ 1][j] = nv;
                mys += nv;
            } else {
                g_jc[j].z = bse + inv * acc2;        // bias for batch step
            }
        }
        if (t == NWARM) break;

        #pragma unroll
        for (int o = 16; o > 0; o >>= 1) mys += __shfl_xor_sync(0xffffffffu, mys, o);
        if (lane == 0) warpS[wid] = mys;
        __syncthreads();
        s = warpS[0] + warpS[1];
        cur ^= 1;
    }
}

// ---------------- kernel C: batch step via factorized kernel evaluation --
// 32 rows/block, 256 threads (8 warps). Warp w evals cols j = w + 8*idx.
// 8-wide explicit load batching for MLP.
struct MainSmem {
    float  Xs[64 * 32];       // [k][row]
    float2 Te[65 * 32];       // [pos][row]  (PAe, PBe)
    float2 Ti[65 * 32];       // [pos][row]  (PAi, PBi)
    float  Yout[64 * 32];     // [col][row]
    float  TBe[32], TBi[32];
    float  warpS[8][32];
    float  sInv[32];
};

__global__ void __launch_bounds__(256) kmain(const float* __restrict__ X,
                                             float* __restrict__ out) {
    extern __shared__ float _smraw[];
    MainSmem* S = (MainSmem*)_smraw;
    const int tid = threadIdx.x, lane = tid & 31, w = tid >> 5;
    const int rowbase = blockIdx.x * 32;

    // load X transposed: thread -> row (tid>>3), k-range (tid&7)*8..+7
    {
        int r = tid >> 3, kq = (tid & 7) * 8;
        const float* xp = &X[(rowbase + r) * NI + kq];
        #pragma unroll
        for (int u = 0; u < 8; u += 4) {
            float4 vv = *(const float4*)&xp[u];
            S->Xs[(kq + u + 0) * 32 + r] = vv.x;
            S->Xs[(kq + u + 1) * 32 + r] = vv.y;
            S->Xs[(kq + u + 2) * 32 + r] = vv.z;
            S->Xs[(kq + u + 3) * 32 + r] = vv.w;
        }
    }
    __syncthreads();

    // build prefix tables: warp 0 -> Te, warp 1 -> Ti (others idle briefly)
    if (w < 2) {
        const int*   gp = (w == 0) ? g_bge : g_bgi;
        const float* gw = (w == 0) ? g_we64 : g_wi64;
        const float* gv = (w == 0) ? g_ve64 : g_vi64;
        float2* T = (w == 0) ? S->Te : S->Ti;
        float pa = 0.f, pb = 0.f;
        #pragma unroll 8
        for (int r = 0; r < 64; r++) {
            T[r * 32 + lane] = make_float2(pa, pb);
            float xv = S->Xs[__ldg(&gp[r]) * 32 + lane];
            pa = fmaf(xv, __ldg(&gw[r]), pa);
            pb = fmaf(xv, __ldg(&gv[r]), pb);
        }
        T[64 * 32 + lane] = make_float2(pa, pb);
        if (w == 0) S->TBe[lane] = pb; else S->TBi[lane] = pb;
    }
    __syncthreads();

    const float TBd = S->TBe[lane] - S->TBi[lane];
    float s = 0.f;
    for (int q0 = 0; q0 < 15; q0++) {                // 15 chunks of 8 cols
        // batch-load 8 column descriptors (8 LDG.128 in flight)
        float4 co[8];
        #pragma unroll
        for (int u = 0; u < 8; u++)
            co[u] = __ldg(&g_jc[w + 8 * (q0 * 8 + u)]);
        // batch the 16 LDS
        float2 te[8], ti[8];
        #pragma unroll
        for (int u = 0; u < 8; u++) {
            int qp = __float_as_int(co[u].w);        // small-part positions: correct here
            te[u] = S->Te[(qp & 0xffff) * 32 + lane];
            ti[u] = S->Ti[(qp >> 16) * 32 + lane];
        }
        #pragma unroll
        for (int u = 0; u < 8; u++) {
            float A  = te[u].x - ti[u].x;
            float Bv = TBd - (te[u].y - ti[u].y);
            float z  = fmaf(co[u].y, Bv, fmaf(co[u].x, A, co[u].z));
            float yv = fmaxf(z, 0.f);
            s += yv;
            if (q0 == 0)                              // j = w+8u < 64 exactly here
                S->Yout[(w + 8 * u) * 32 + lane] = yv;
        }
    }
    S->warpS[w][lane] = s;
    __syncthreads();
    if (w == 0) {
        float stot = ((S->warpS[0][lane] + S->warpS[1][lane])
                   +  (S->warpS[2][lane] + S->warpS[3][lane]))
                   + ((S->warpS[4][lane] + S->warpS[5][lane])
                   +  (S->warpS[6][lane] + S->warpS[7][lane]));
        S->sInv[lane] = (stot > 0.f) ? (1.0f / stot) : 1.0f;
    }
    __syncthreads();

    // write out: thread -> row (tid>>3), cols (tid&7)*8..+7
    {
        int r = tid >> 3, c0 = (tid & 7) * 8;
        float inv = S->sInv[r];
        float* op = &out[(rowbase + r) * NO + c0];
        #pragma unroll
        for (int u = 0; u < 8; u += 4) {
            float4 vv = make_float4(S->Yout[(c0 + u + 0) * 32 + r] * inv,
                                    S->Yout[(c0 + u + 1) * 32 + r] * inv,
                                    S->Yout[(c0 + u + 2) * 32 + r] * inv,
                                    S->Yout[(c0 + u + 3) * 32 + r] * inv);
            *(float4*)&op[u] = vv;
        }
    }
}

// ---------------- launch ---------------------------------------------------
extern "C" void kernel_launch(void* const* d_in, const int* in_sizes, int n_in,
                              void* d_out, int out_size) {
    const float* X     = (const float*)d_in[0];  // (16384, 64)
    const float* ident = (const float*)d_in[1];  // (1024,)
    const float* enh   = (const float*)d_in[2];  // (1024,)
    const float* inh   = (const float*)d_in[3];  // (1024,)
    const float* beta  = (const float*)d_in[4];  // (1,)
    const float* delta = (const float*)d_in[5];  // (1,)
    (void)in_sizes; (void)n_in; (void)out_size;

    cudaFuncSetAttribute(kmain, cudaFuncAttributeMaxDynamicSharedMemorySize,
                         (int)sizeof(MainSmem));

    kprep<<<JCOLS, 128>>>(ident, enh, inh, beta, delta);
    kwarm<<<1, 64>>>(delta);
    kmain<<<NB / 32, 256, sizeof(MainSmem)>>>(X, (float*)d_out);
}